// round 3
// baseline (speedup 1.0000x reference)
#include <cuda_runtime.h>
#include <cstdint>

#define TSTEPS 1024
#define BATCH  256
#define INSZ   128
#define HID    512
#define OUTSZ  32
#define RB     16      // batch rows per cluster
#define JT     64      // hidden outputs per CTA
#define CLUSZ  8       // CTAs per cluster

// scratch (device globals: the sanctioned no-alloc workaround)
__device__ float g_xproj[(size_t)TSTEPS * BATCH * HID];   // 512 MB
__device__ float g_h[2][BATCH * HID];                     // double-buffered state

// ---------------------------------------------------------------------------
// Kernel 1: x_proj[t,b,:] = inputs[t,b,:] @ W_in + b_rec    (M=262144,K=128,N=512)
// ---------------------------------------------------------------------------
__global__ void __launch_bounds__(256, 1)
xproj_kernel(const float* __restrict__ in, const float* __restrict__ Win,
             const float* __restrict__ brec)
{
    extern __shared__ float sm1[];
    float*  As  = sm1;               // [128][132] padded
    float4* As4 = (float4*)As;
    float*  Bs  = sm1 + 128 * 132;   // [128][128]
    float4* Bs4 = (float4*)Bs;

    const int tid = threadIdx.x;
    const int m0  = blockIdx.x * 128;
    const int n0  = blockIdx.y * 128;

    for (int i = tid; i < 4096; i += 256) {
        int m = i >> 5, kq = i & 31;
        As4[m * 33 + kq] = *(const float4*)(in + (size_t)(m0 + m) * INSZ + kq * 4);
    }
    for (int i = tid; i < 4096; i += 256) {
        int k = i >> 5, nq = i & 31;
        Bs4[k * 32 + nq] = *(const float4*)(Win + (size_t)k * HID + n0 + nq * 4);
    }
    __syncthreads();

    const int tx = tid & 15, ty = tid >> 4;
    const int mm = ty * 8,   nn = tx * 8;

    float acc[8][8];
#pragma unroll
    for (int i = 0; i < 8; i++)
#pragma unroll
        for (int jj = 0; jj < 8; jj++) acc[i][jj] = 0.f;

#pragma unroll 4
    for (int k = 0; k < 128; k++) {
        float a[8];
#pragma unroll
        for (int i = 0; i < 8; i++) a[i] = As[(mm + i) * 132 + k];
        float4 bv0 = Bs4[k * 32 + (nn >> 2)];
        float4 bv1 = Bs4[k * 32 + (nn >> 2) + 1];
        float b[8] = {bv0.x, bv0.y, bv0.z, bv0.w, bv1.x, bv1.y, bv1.z, bv1.w};
#pragma unroll
        for (int i = 0; i < 8; i++)
#pragma unroll
            for (int jj = 0; jj < 8; jj++) acc[i][jj] = fmaf(a[i], b[jj], acc[i][jj]);
    }

    float4 br0 = *(const float4*)(brec + n0 + nn);
    float4 br1 = *(const float4*)(brec + n0 + nn + 4);
#pragma unroll
    for (int i = 0; i < 8; i++) {
        float4 s0 = make_float4(acc[i][0] + br0.x, acc[i][1] + br0.y,
                                acc[i][2] + br0.z, acc[i][3] + br0.w);
        float4 s1 = make_float4(acc[i][4] + br1.x, acc[i][5] + br1.y,
                                acc[i][6] + br1.z, acc[i][7] + br1.w);
        float* dst = g_xproj + (size_t)(m0 + mm + i) * HID + n0 + nn;
        *(float4*)dst       = s0;
        *(float4*)(dst + 4) = s1;
    }
}

// ---------------------------------------------------------------------------
// Kernel 2: persistent recurrence + fused output projection
// grid = 128 CTAs = 16 clusters x 8; cluster c owns batch rows [16c, 16c+16);
// CTA rank r owns hidden slice [64r, 64r+64); W_rec slice lives in registers.
// ---------------------------------------------------------------------------
// smem layout (floats)
#define SM2_H     0                   // [16][512]
#define SM2_PART  (16 * 512)          // [16][4][64]
#define SM2_OPART (SM2_PART + 4096)   // [4][64]
#define SM2_XP    (SM2_OPART + 256)   // [16][64]
#define SM2_WOUT  (SM2_XP + 1024)     // [512][32]
#define SM2_BOUT  (SM2_WOUT + 16384)  // [32]
#define SM2_BYTES ((SM2_BOUT + 32) * 4)   // 119936 bytes

__global__ void __cluster_dims__(CLUSZ, 1, 1) __launch_bounds__(256, 1)
rnn_kernel(const float* __restrict__ Wrec, const float* __restrict__ Wout,
           const float* __restrict__ bout, float* __restrict__ out)
{
    extern __shared__ float sm[];
    float*  sh_h     = sm + SM2_H;
    float4* sh_h4    = (float4*)sh_h;
    float*  sh_part  = sm + SM2_PART;
    float*  sh_opart = sm + SM2_OPART;
    float*  sh_xp    = sm + SM2_XP;
    float*  sh_wout  = sm + SM2_WOUT;
    float*  sh_bout  = sm + SM2_BOUT;

    const int tid   = threadIdx.x;
    const int rank  = blockIdx.x & (CLUSZ - 1);
    const int clu   = blockIdx.x >> 3;
    const int b0    = clu * RB;
    const int jbase = rank * JT;

    const int j    = tid & 63;
    const int kseg = tid >> 6;           // 4 k-segments of 128

    // resident W_rec slice: thread holds W_rec[jbase+j][kseg*128 .. +128)
    float4 W4[32];
    {
        const float4* wr = (const float4*)(Wrec + (size_t)(jbase + j) * HID + kseg * 128);
#pragma unroll
        for (int q = 0; q < 32; q++) W4[q] = wr[q];
    }
    // W_out / b_out to smem (consumed from s=1 on; syncs in-loop cover visibility)
    {
        const float4* wg = (const float4*)Wout;
        float4* ws = (float4*)sh_wout;
        for (int i = tid; i < HID * OUTSZ / 4; i += 256) ws[i] = wg[i];
        if (tid < OUTSZ) sh_bout[tid] = bout[tid];
    }

    // output-projection thread mapping: el = (row2, o), 4-way k-split
    const int orow_el    = tid & 63;
    const int oo         = orow_el & 31;
    const int orow_local = 2 * rank + (orow_el >> 5);
    const int oksub      = tid >> 6;

    for (int s = 0; s < TSTEPS; ++s) {
        // ---- load H_s (full 16x512) and xp tile ----
        if (s == 0) {
            float4 z = make_float4(0.f, 0.f, 0.f, 0.f);
#pragma unroll
            for (int u = 0; u < 8; u++) sh_h4[tid + 256 * u] = z;
        } else {
            const float4* hs = (const float4*)(g_h[s & 1] + (size_t)b0 * HID);
#pragma unroll
            for (int u = 0; u < 8; u++)
                sh_h4[tid + 256 * u] = __ldcv(hs + tid + 256 * u);
        }
        {
            const float* xs = g_xproj + ((size_t)s * BATCH + b0) * HID + jbase;
            int bb = tid >> 4, jq = tid & 15;
            ((float4*)sh_xp)[bb * 16 + jq] = *(const float4*)(xs + (size_t)bb * HID + jq * 4);
        }
        __syncthreads();

        // ---- output projection (accumulate) for step s-1: uses H_s = hs[s-1] ----
        if (s > 0) {
            const float* hr = sh_h + orow_local * HID + oksub * 128;
            const float* wc = sh_wout + oksub * 128 * OUTSZ + oo;
            float oa0 = 0.f, oa1 = 0.f;
#pragma unroll 8
            for (int k = 0; k < 128; k += 2) {
                oa0 = fmaf(hr[k],     wc[k * OUTSZ],       oa0);
                oa1 = fmaf(hr[k + 1], wc[(k + 1) * OUTSZ], oa1);
            }
            sh_opart[oksub * 64 + orow_el] = oa0 + oa1;
        }

        // ---- recurrent matmul partials: pre[b][j] over this k-segment ----
        {
            const float4* hb = sh_h4 + kseg * 32;
#pragma unroll 1
            for (int b = 0; b < RB; b++) {
                const float4* hrow = hb + b * (HID / 4);
                float ax = 0.f, ay = 0.f, az = 0.f, aw = 0.f;
#pragma unroll
                for (int q = 0; q < 32; q++) {
                    float4 hv = hrow[q];
                    ax = fmaf(W4[q].x, hv.x, ax);
                    ay = fmaf(W4[q].y, hv.y, ay);
                    az = fmaf(W4[q].z, hv.z, az);
                    aw = fmaf(W4[q].w, hv.w, aw);
                }
                sh_part[(b * 4 + kseg) * 64 + j] = (ax + ay) + (az + aw);
            }
        }
        __syncthreads();

        // ---- state update: H_{s+1} tile ----
        {
            float* hdst = g_h[(s + 1) & 1] + (size_t)b0 * HID + jbase;
#pragma unroll
            for (int u = 0; u < 4; u++) {
                int idx = tid + 256 * u;
                int b = idx >> 6, jj = idx & 63;
                float pre = (sh_part[(b * 4 + 0) * 64 + jj] + sh_part[(b * 4 + 1) * 64 + jj])
                          + (sh_part[(b * 4 + 2) * 64 + jj] + sh_part[(b * 4 + 3) * 64 + jj]);
                float act = pre + sh_xp[b * 64 + jj];
                act = act > 0.f ? act : 0.f;
                float hn = 0.999f * sh_h[b * HID + jbase + jj] + 0.001f * act;
                hdst[(size_t)b * HID + jj] = hn;
            }
        }
        // ---- output projection (finalize) for step s-1 ----
        if (s > 0 && tid < 64) {
            float v = sh_opart[tid] + sh_opart[64 + tid] + sh_opart[128 + tid]
                    + sh_opart[192 + tid] + sh_bout[tid & 31];
            int row = b0 + 2 * rank + (tid >> 5);
            out[((size_t)(s - 1) * BATCH + row) * OUTSZ + (tid & 31)] = v;
        }

        __threadfence();   // publish H_{s+1} stores to L2 (gpu scope)
        asm volatile("barrier.cluster.arrive.aligned;" ::: "memory");
        asm volatile("barrier.cluster.wait.aligned;"   ::: "memory");
    }

    // ---- epilogue: out[1023] from H_1024 (in g_h[0]) ----
    {
        const float4* hs = (const float4*)(g_h[0] + (size_t)b0 * HID);
#pragma unroll
        for (int u = 0; u < 8; u++)
            sh_h4[tid + 256 * u] = __ldcv(hs + tid + 256 * u);
        __syncthreads();
        {
            const float* hr = sh_h + orow_local * HID + oksub * 128;
            const float* wc = sh_wout + oksub * 128 * OUTSZ + oo;
            float oa0 = 0.f, oa1 = 0.f;
#pragma unroll 8
            for (int k = 0; k < 128; k += 2) {
                oa0 = fmaf(hr[k],     wc[k * OUTSZ],       oa0);
                oa1 = fmaf(hr[k + 1], wc[(k + 1) * OUTSZ], oa1);
            }
            sh_opart[oksub * 64 + orow_el] = oa0 + oa1;
        }
        __syncthreads();
        if (tid < 64) {
            float v = sh_opart[tid] + sh_opart[64 + tid] + sh_opart[128 + tid]
                    + sh_opart[192 + tid] + sh_bout[tid & 31];
            int row = b0 + 2 * rank + (tid >> 5);
            out[((size_t)(TSTEPS - 1) * BATCH + row) * OUTSZ + (tid & 31)] = v;
        }
    }
}

// ---------------------------------------------------------------------------
extern "C" void kernel_launch(void* const* d_in, const int* in_sizes, int n_in,
                              void* d_out, int out_size)
{
    const float* inputs = (const float*)d_in[0];
    const float* Wrec   = (const float*)d_in[1];
    const float* Win    = (const float*)d_in[2];
    const float* brec   = (const float*)d_in[3];
    const float* Wout   = (const float*)d_in[4];
    const float* bout   = (const float*)d_in[5];
    float* out = (float*)d_out;

    const int smem1 = (128 * 132 + 128 * 128) * 4;   // 133120
    cudaFuncSetAttribute(xproj_kernel, cudaFuncAttributeMaxDynamicSharedMemorySize, smem1);
    cudaFuncSetAttribute(rnn_kernel,   cudaFuncAttributeMaxDynamicSharedMemorySize, SM2_BYTES);

    dim3 g1((TSTEPS * BATCH) / 128, HID / 128);
    xproj_kernel<<<g1, 256, smem1>>>(inputs, Win, brec);

    rnn_kernel<<<128, 256, SM2_BYTES>>>(Wrec, Wout, bout, out);

    (void)in_sizes; (void)n_in; (void)out_size;
}

// round 5
// speedup vs baseline: 1.1619x; 1.1619x over previous
#include <cuda_runtime.h>
#include <cstdint>

#define TSTEPS 1024
#define BATCH  256
#define INSZ   128
#define HID    512
#define OUTSZ  32
#define RB     16      // batch rows per cluster
#define JT     64      // hidden outputs per CTA
#define CLUSZ  8       // CTAs per cluster
#define THR2   512     // threads per rnn CTA

// scratch (device globals: the sanctioned no-alloc workaround)
__device__ float g_xproj[(size_t)TSTEPS * BATCH * HID];   // 512 MB
__device__ float g_h[2][BATCH * HID];                     // double-buffered state

// ---------------- packed f32x2 helpers (sm_103a FFMA2) ----------------
__device__ __forceinline__ void fma2(unsigned long long& d,
                                     unsigned long long a,
                                     unsigned long long b) {
    asm("fma.rn.f32x2 %0, %1, %2, %0;" : "+l"(d) : "l"(a), "l"(b));
}
__device__ __forceinline__ unsigned long long splat2(float a) {
    unsigned long long r;
    asm("mov.b64 %0, {%1, %1};" : "=l"(r) : "f"(a));
    return r;
}
__device__ __forceinline__ float2 unpk(unsigned long long v) {
    float2 f;
    asm("mov.b64 {%0, %1}, %2;" : "=f"(f.x), "=f"(f.y) : "l"(v));
    return f;
}

// ---------------------------------------------------------------------------
// Kernel 1: x_proj[t,b,:] = inputs[t,b,:] @ W_in + b_rec   (M=262144,K=128,N=512)
// ---------------------------------------------------------------------------
__global__ void __launch_bounds__(256, 1)
xproj_kernel(const float* __restrict__ in, const float* __restrict__ Win,
             const float* __restrict__ brec)
{
    extern __shared__ float sm1[];
    float*  As  = sm1;               // [128][132] padded
    float4* As4 = (float4*)As;
    float*  Bs  = sm1 + 128 * 132;   // [128][128]
    float4* Bs4 = (float4*)Bs;

    const int tid = threadIdx.x;
    const int m0  = blockIdx.x * 128;
    const int n0  = blockIdx.y * 128;

    for (int i = tid; i < 4096; i += 256) {
        int m = i >> 5, kq = i & 31;
        As4[m * 33 + kq] = *(const float4*)(in + (size_t)(m0 + m) * INSZ + kq * 4);
    }
    for (int i = tid; i < 4096; i += 256) {
        int k = i >> 5, nq = i & 31;
        Bs4[k * 32 + nq] = *(const float4*)(Win + (size_t)k * HID + n0 + nq * 4);
    }
    __syncthreads();

    const int tx = tid & 15, ty = tid >> 4;
    const int mm = ty * 8,   nn = tx * 8;

    unsigned long long accq[8][4];
#pragma unroll
    for (int i = 0; i < 8; i++)
#pragma unroll
        for (int jj = 0; jj < 4; jj++) accq[i][jj] = 0ULL;

#pragma unroll 4
    for (int k = 0; k < 128; k++) {
        unsigned long long aa[8];
#pragma unroll
        for (int i = 0; i < 8; i++) aa[i] = splat2(As[(mm + i) * 132 + k]);
        const ulonglong2* bq = (const ulonglong2*)(Bs4 + k * 32 + (nn >> 2));
        ulonglong2 bA = bq[0];
        ulonglong2 bB = bq[1];
#pragma unroll
        for (int i = 0; i < 8; i++) {
            fma2(accq[i][0], aa[i], bA.x);
            fma2(accq[i][1], aa[i], bA.y);
            fma2(accq[i][2], aa[i], bB.x);
            fma2(accq[i][3], aa[i], bB.y);
        }
    }

    float4 br0 = *(const float4*)(brec + n0 + nn);
    float4 br1 = *(const float4*)(brec + n0 + nn + 4);
#pragma unroll
    for (int i = 0; i < 8; i++) {
        float2 p0 = unpk(accq[i][0]), p1 = unpk(accq[i][1]);
        float2 p2 = unpk(accq[i][2]), p3 = unpk(accq[i][3]);
        float4 s0 = make_float4(p0.x + br0.x, p0.y + br0.y, p1.x + br0.z, p1.y + br0.w);
        float4 s1 = make_float4(p2.x + br1.x, p2.y + br1.y, p3.x + br1.z, p3.y + br1.w);
        float* dst = g_xproj + (size_t)(m0 + mm + i) * HID + n0 + nn;
        *(float4*)dst       = s0;
        *(float4*)(dst + 4) = s1;
    }
}

// ---------------------------------------------------------------------------
// Kernel 2: persistent recurrence + fused output projection, 512 threads/CTA.
// grid = 128 CTAs = 16 clusters x 8; cluster c owns batch rows [16c, 16c+16);
// CTA rank r owns hidden slice [64r, 64r+64); W_rec slice resident in regs
// as f32x2 pairs: thread owns the FULL 64-wide k-segment of row jbase+j
// (64 floats = 16 ulonglong2 = 64 registers).
// ---------------------------------------------------------------------------
// smem layout (floats)
#define SM2_H     0                      // [16][512]
#define SM2_PART  (16 * 512)             // [16][8][64]
#define SM2_OPART (SM2_PART + 8192)      // [8][64]
#define SM2_XP    (SM2_OPART + 512)      // [16][64]
#define SM2_WOUT  (SM2_XP + 1024)        // [512][32]
#define SM2_BOUT  (SM2_WOUT + 16384)     // [32]
#define SM2_BYTES ((SM2_BOUT + 32) * 4)  // 137472 bytes

__global__ void __cluster_dims__(CLUSZ, 1, 1) __launch_bounds__(THR2, 1)
rnn_kernel(const float* __restrict__ Wrec, const float* __restrict__ Wout,
           const float* __restrict__ bout, float* __restrict__ out)
{
    extern __shared__ float sm[];
    float*  sh_h     = sm + SM2_H;
    float4* sh_h4    = (float4*)sh_h;
    float*  sh_part  = sm + SM2_PART;
    float*  sh_opart = sm + SM2_OPART;
    float*  sh_xp    = sm + SM2_XP;
    float*  sh_wout  = sm + SM2_WOUT;
    float*  sh_bout  = sm + SM2_BOUT;

    const int tid   = threadIdx.x;
    const int rank  = blockIdx.x & (CLUSZ - 1);
    const int clu   = blockIdx.x >> 3;
    const int b0    = clu * RB;
    const int jbase = rank * JT;

    const int j    = tid & 63;
    const int kseg = tid >> 6;           // 8 k-segments of 64

    // resident W_rec slice as f32x2 pairs: W_rec[jbase+j][kseg*64 .. +64)
    // 64 floats = 32 pairs = 16 ulonglong2   (this was 8 in R4 — the bug)
    ulonglong2 W2[16];
    {
        const ulonglong2* wr =
            (const ulonglong2*)(Wrec + (size_t)(jbase + j) * HID + kseg * 64);
#pragma unroll
        for (int q = 0; q < 16; q++) W2[q] = wr[q];
    }
    // W_out / b_out to smem (consumed from s=1 on; first syncthreads covers it)
    {
        const float4* wg = (const float4*)Wout;
        float4* ws = (float4*)sh_wout;
        for (int i = tid; i < HID * OUTSZ / 4; i += THR2) ws[i] = wg[i];
        if (tid < OUTSZ) sh_bout[tid] = bout[tid];
    }

    // output-projection thread mapping: 2 rows x 32 outs, 8-way k-split (64 each)
    const int orow_el    = tid & 63;
    const int oo         = orow_el & 31;
    const int orow_local = 2 * rank + (orow_el >> 5);
    const int oksub      = tid >> 6;

    // xp prefetch: threads < 256 each hold one float4 of the [16][64] tile
    const int xb = tid >> 4, xq = tid & 15;
    float4 xpr = make_float4(0.f, 0.f, 0.f, 0.f);
    if (tid < 256)
        xpr = *(const float4*)(g_xproj + ((size_t)0 * BATCH + b0 + xb) * HID
                               + jbase + xq * 4);

    for (int s = 0; s < TSTEPS; ++s) {
        // ---- load H_s (full 16x512) ----
        if (s == 0) {
            float4 z = make_float4(0.f, 0.f, 0.f, 0.f);
#pragma unroll
            for (int u = 0; u < 4; u++) sh_h4[tid + THR2 * u] = z;
        } else {
            const float4* hs = (const float4*)(g_h[s & 1] + (size_t)b0 * HID);
#pragma unroll
            for (int u = 0; u < 4; u++)
                sh_h4[tid + THR2 * u] = __ldcv(hs + tid + THR2 * u);
        }
        // publish prefetched xp, then start prefetch for s+1 (hidden by compute)
        if (tid < 256) {
            ((float4*)sh_xp)[tid] = xpr;
            if (s + 1 < TSTEPS)
                xpr = *(const float4*)(g_xproj + ((size_t)(s + 1) * BATCH + b0 + xb) * HID
                                       + jbase + xq * 4);
        }
        __syncthreads();

        // ---- output projection (accumulate) for step s-1: uses H_s = hs[s-1] ----
        if (s > 0) {
            const float* hr = sh_h + orow_local * HID + oksub * 64;
            const float* wc = sh_wout + oksub * 64 * OUTSZ + oo;
            float oa0 = 0.f, oa1 = 0.f;
#pragma unroll 8
            for (int k = 0; k < 64; k += 2) {
                oa0 = fmaf(hr[k],     wc[k * OUTSZ],       oa0);
                oa1 = fmaf(hr[k + 1], wc[(k + 1) * OUTSZ], oa1);
            }
            sh_opart[oksub * 64 + orow_el] = oa0 + oa1;
        }

        // ---- recurrent matmul partials: pre[b][j] over this 64-wide k-segment ----
        {
            const float* hbase = sh_h + kseg * 64;
#pragma unroll 1
            for (int b = 0; b < RB; b++) {
                const ulonglong2* hrow = (const ulonglong2*)(hbase + b * HID);
                unsigned long long a01 = 0ULL, a23 = 0ULL;
#pragma unroll
                for (int q = 0; q < 16; q++) {
                    ulonglong2 hv = hrow[q];
                    fma2(a01, W2[q].x, hv.x);
                    fma2(a23, W2[q].y, hv.y);
                }
                float2 u = unpk(a01), v = unpk(a23);
                sh_part[(b * 8 + kseg) * 64 + j] = (u.x + u.y) + (v.x + v.y);
            }
        }
        __syncthreads();

        // ---- state update: H_{s+1} tile (float2 per thread: 16b x 32 pairs) ----
        {
            const int b  = tid >> 5;
            const int jh = (tid & 31) * 2;
            float2 pre = make_float2(0.f, 0.f);
#pragma unroll
            for (int k = 0; k < 8; k++) {
                float2 p = *(const float2*)&sh_part[(b * 8 + k) * 64 + jh];
                pre.x += p.x; pre.y += p.y;
            }
            float2 xpv  = *(const float2*)&sh_xp[b * 64 + jh];
            float2 hold = *(const float2*)&sh_h[b * HID + jbase + jh];
            float ax = pre.x + xpv.x; ax = ax > 0.f ? ax : 0.f;
            float ay = pre.y + xpv.y; ay = ay > 0.f ? ay : 0.f;
            float2 hn = make_float2(0.999f * hold.x + 0.001f * ax,
                                    0.999f * hold.y + 0.001f * ay);
            *(float2*)(g_h[(s + 1) & 1] + (size_t)(b0 + b) * HID + jbase + jh) = hn;
        }
        // ---- output projection (finalize) for step s-1 ----
        if (s > 0 && tid < 64) {
            float v = ((sh_opart[tid]       + sh_opart[64 + tid])
                     + (sh_opart[128 + tid] + sh_opart[192 + tid]))
                    + ((sh_opart[256 + tid] + sh_opart[320 + tid])
                     + (sh_opart[384 + tid] + sh_opart[448 + tid]))
                    + sh_bout[tid & 31];
            int row = b0 + 2 * rank + (tid >> 5);
            out[((size_t)(s - 1) * BATCH + row) * OUTSZ + (tid & 31)] = v;
        }

        // cluster barrier: arrive has release semantics (cluster scope), wait has
        // acquire — publishes the H_{s+1} global stores; peers read via __ldcv.
        asm volatile("barrier.cluster.arrive.aligned;" ::: "memory");
        asm volatile("barrier.cluster.wait.aligned;"   ::: "memory");
    }

    // ---- epilogue: out[1023] from H_1024 (in g_h[0]) ----
    {
        const float4* hs = (const float4*)(g_h[0] + (size_t)b0 * HID);
#pragma unroll
        for (int u = 0; u < 4; u++)
            sh_h4[tid + THR2 * u] = __ldcv(hs + tid + THR2 * u);
        __syncthreads();
        {
            const float* hr = sh_h + orow_local * HID + oksub * 64;
            const float* wc = sh_wout + oksub * 64 * OUTSZ + oo;
            float oa0 = 0.f, oa1 = 0.f;
#pragma unroll 8
            for (int k = 0; k < 64; k += 2) {
                oa0 = fmaf(hr[k],     wc[k * OUTSZ],       oa0);
                oa1 = fmaf(hr[k + 1], wc[(k + 1) * OUTSZ], oa1);
            }
            sh_opart[oksub * 64 + orow_el] = oa0 + oa1;
        }
        __syncthreads();
        if (tid < 64) {
            float v = ((sh_opart[tid]       + sh_opart[64 + tid])
                     + (sh_opart[128 + tid] + sh_opart[192 + tid]))
                    + ((sh_opart[256 + tid] + sh_opart[320 + tid])
                     + (sh_opart[384 + tid] + sh_opart[448 + tid]))
                    + sh_bout[tid & 31];
            int row = b0 + 2 * rank + (tid >> 5);
            out[((size_t)(TSTEPS - 1) * BATCH + row) * OUTSZ + (tid & 31)] = v;
        }
    }
}

// ---------------------------------------------------------------------------
extern "C" void kernel_launch(void* const* d_in, const int* in_sizes, int n_in,
                              void* d_out, int out_size)
{
    const float* inputs = (const float*)d_in[0];
    const float* Wrec   = (const float*)d_in[1];
    const float* Win    = (const float*)d_in[2];
    const float* brec   = (const float*)d_in[3];
    const float* Wout   = (const float*)d_in[4];
    const float* bout   = (const float*)d_in[5];
    float* out = (float*)d_out;

    const int smem1 = (128 * 132 + 128 * 128) * 4;   // 133120
    cudaFuncSetAttribute(xproj_kernel, cudaFuncAttributeMaxDynamicSharedMemorySize, smem1);
    cudaFuncSetAttribute(rnn_kernel,   cudaFuncAttributeMaxDynamicSharedMemorySize, SM2_BYTES);

    dim3 g1((TSTEPS * BATCH) / 128, HID / 128);
    xproj_kernel<<<g1, 256, smem1>>>(inputs, Win, brec);

    rnn_kernel<<<128, THR2, SM2_BYTES>>>(Wrec, Wout, bout, out);

    (void)in_sizes; (void)n_in; (void)out_size;
}